// round 1
// baseline (speedup 1.0000x reference)
#include <cuda_runtime.h>

#define NB_ITEMS 12000
#define DD 64
#define BB 1024
#define LL 20
#define BKK 10
#define NOLDK 20

#define SIM_OFF   ((size_t)BB * NB_ITEMS)                     /* 12,288,000 */
#define OMIGA_OFF (SIM_OFF + (size_t)NB_ITEMS * NB_ITEMS)     /* 156,288,000 */

// ---------------- scratch (static device globals; no allocation) ----------------
__device__ float g_final_each[4 * BB * DD];   // [n][b][d]
__device__ float g_final[BB * DD];            // [b][d]
__device__ float g_Amat[BB * 128];            // [b][0:64)=final, [64:128)=e_user
__device__ float g_Bbig[(size_t)NB_ITEMS * 128]; // [e][0:64)=item_emb[1+e], [64:128)=u_w[:,e]

// ---------------- f32x2 helpers (packed fp32 FMA, sm_100+) ----------------
typedef unsigned long long u64;
__device__ __forceinline__ u64 bcast2(float x) {
    u64 r; asm("mov.b64 %0, {%1, %1};" : "=l"(r) : "f"(x)); return r;
}
__device__ __forceinline__ void fma2(u64& d, u64 a, u64 b) {
    asm("fma.rn.f32x2 %0, %1, %2, %0;" : "+l"(d) : "l"(a), "l"(b));
}
__device__ __forceinline__ void unpk2(u64 v, float& lo, float& hi) {
    asm("mov.b64 {%0, %1}, %2;" : "=f"(lo), "=f"(hi) : "l"(v));
}
__device__ __forceinline__ float sigmoidf_(float x) { return 1.f / (1.f + expf(-x)); }

// ---------------- prep: build Bbig (e_all || u_w^T) and copy omiga ----------------
__global__ __launch_bounds__(256) void prep_kernel(
    const float* __restrict__ item_emb, const float* __restrict__ u_w,
    const float* __restrict__ omiga, float* __restrict__ out)
{
    int idx = blockIdx.x * blockDim.x + threadIdx.x;
    if (idx < NB_ITEMS * 128) {
        int e = idx >> 7, k = idx & 127;
        g_Bbig[idx] = (k < 64) ? item_emb[(size_t)(e + 1) * 64 + k]
                               : u_w[(size_t)(k - 64) * NB_ITEMS + e];
    }
    if (idx < NB_ITEMS) out[OMIGA_OFF + idx] = omiga[idx + 1];
}

// ---------------- per-batch kernel: baskets/attn/ema/gates/mix ----------------
__global__ __launch_bounds__(256) void batch_kernel(
    const int* __restrict__ click, const int* __restrict__ favor,
    const int* __restrict__ cart, const int* __restrict__ buy,
    const int* __restrict__ userData,
    const float* __restrict__ item_emb, const float* __restrict__ user_emb,
    const float* __restrict__ user_wd, const float* __restrict__ w_mix,
    const float* __restrict__ alpha, const float* __restrict__ gate_w,
    const float* __restrict__ gate_b, const float* __restrict__ Wk,
    const float* __restrict__ bk)
{
    __shared__ float s_bask[4][LL][DD];
    __shared__ int   s_idx[4][LL][BKK];
    __shared__ float s_eu[DD];
    __shared__ float s_scp[4][2][LL];
    __shared__ float s_attn[4][LL];
    __shared__ float s_mask[4][LL];
    __shared__ float s_lvec[4][DD];
    __shared__ float s_s1[4][DD], s_s2[4][DD], s_s3[4][DD], s_fn[4][DD];
    __shared__ float s_g[8];
    __shared__ float s_fm[DD], s_lm[DD];

    int b = blockIdx.x, t = threadIdx.x;
    int lane = t & 31, warp = t >> 5;
    int u = userData[b];
    const int* srcs[4] = {click, favor, cart, buy};

    for (int i = t; i < 4 * LL * BKK; i += 256) {
        int n = i / (LL * BKK), r = i % (LL * BKK);
        s_idx[n][r / BKK][r % BKK] = srcs[n][(size_t)b * LL * BKK + r];
    }
    if (t < 64) s_eu[t] = user_emb[(size_t)u * 64 + t];
    __syncthreads();

    // baskets: sum of 10 gathered embeddings per (n,l,d)
    for (int i = t; i < 4 * LL * DD; i += 256) {
        int n = i / (LL * DD), rem = i % (LL * DD), l = rem / DD, d = rem & 63;
        float s = 0.f;
        #pragma unroll
        for (int q = 0; q < BKK; q++) s += item_emb[(size_t)s_idx[n][l][q] * 64 + d];
        s_bask[n][l][d] = s;
    }
    __syncthreads();

    // posmask
    if (t < 80) {
        int n = t / LL, l = t % LL;
        float m = 0.f;
        for (int d = 0; d < DD; d++) m += s_bask[n][l][d];
        s_mask[n][l] = (m != 0.f) ? 1.f : 0.f;
    }

    // k = relu(bask @ Wk[n] + bk), scores = e_user . k   (thread = (n,e))
    {
        int n = t >> 6, e = t & 63;
        float acc[LL];
        #pragma unroll
        for (int l = 0; l < LL; l++) acc[l] = bk[n * 64 + e];
        for (int d0 = 0; d0 < DD; d0++) {
            float w = Wk[((size_t)n * 64 + d0) * 64 + e];
            #pragma unroll
            for (int l = 0; l < LL; l++) acc[l] += s_bask[n][l][d0] * w;
        }
        float eu = s_eu[e];
        #pragma unroll
        for (int l = 0; l < LL; l++) {
            float v = fmaxf(acc[l], 0.f) * eu;
            #pragma unroll
            for (int o = 16; o > 0; o >>= 1) v += __shfl_xor_sync(0xffffffffu, v, o);
            if (lane == 0) s_scp[n][e >> 5][l] = v;
        }
    }
    __syncthreads();

    // softmax over l per n
    if (warp < 4) {
        int n = warp;
        float sc = -1e30f;
        if (lane < LL) {
            sc = (s_scp[n][0][lane] + s_scp[n][1][lane]) * 0.125f;
            if (s_mask[n][lane] == 0.f) sc = -1e9f;
        }
        float mx = sc;
        #pragma unroll
        for (int o = 16; o > 0; o >>= 1) mx = fmaxf(mx, __shfl_xor_sync(0xffffffffu, mx, o));
        float ex = (lane < LL) ? expf(sc - mx) : 0.f;
        float sm = ex;
        #pragma unroll
        for (int o = 16; o > 0; o >>= 1) sm += __shfl_xor_sync(0xffffffffu, sm, o);
        if (lane < LL) s_attn[n][lane] = ex / sm;
    }
    __syncthreads();

    // l_vec + EMA (thread = (n,d))
    {
        int n = t >> 6, d = t & 63;
        float lv = 0.f;
        #pragma unroll
        for (int l = 0; l < LL; l++) lv += s_attn[n][l] * s_bask[n][l][d];
        s_lvec[n][d] = lv;
        float w1 = sigmoidf_(user_wd[(size_t)u * 8 + 2 * n]);
        float w2 = sigmoidf_(user_wd[(size_t)u * 8 + 2 * n + 1]);
        float coef = 1.f - w2 * w1;
        float h = s_bask[n][0][d];
        #pragma unroll
        for (int l = 1; l < LL; l++) h = w1 * h + coef * s_bask[n][l][d];
        float s1 = h;
        h = s_bask[n][10][d];
        #pragma unroll
        for (int l = 11; l < LL; l++) h = w1 * h + coef * s_bask[n][l][d];
        float s2 = h;
        float s3 = w1 * s_bask[n][18][d] + coef * s_bask[n][19][d];
        float a0 = alpha[0], a1 = alpha[1];
        float fn = s1 + a0 * (s1 - s2) + a1 * (s1 - s3);
        s_s1[n][d] = s1; s_s2[n][d] = s2; s_s3[n][d] = s3; s_fn[n][d] = fn;
    }
    __syncthreads();

    // per-n gate
    if (warp < 4) {
        int n = warp;
        float x = s_fn[n][lane] * gate_w[lane] + s_fn[n][lane + 32] * gate_w[lane + 32]
                + s_lvec[n][lane] * gate_w[64 + lane] + s_lvec[n][lane + 32] * gate_w[96 + lane];
        #pragma unroll
        for (int o = 16; o > 0; o >>= 1) x += __shfl_xor_sync(0xffffffffu, x, o);
        if (lane == 0) s_g[n] = sigmoidf_(x + gate_b[0]);
    }
    __syncthreads();

    {
        int n = t >> 6, d = t & 63;
        float g = s_g[n];
        g_final_each[((size_t)n * BB + b) * 64 + d] = g * s_fn[n][d] + (1.f - g) * s_lvec[n][d];
    }

    // w_mix softmax + mixed streams
    if (t < 64) {
        int d = t;
        float wmx[4][4];
        #pragma unroll
        for (int i = 0; i < 4; i++) {
            float mx = -1e30f;
            #pragma unroll
            for (int j = 0; j < 4; j++) mx = fmaxf(mx, w_mix[i * 4 + j]);
            float s = 0.f;
            #pragma unroll
            for (int j = 0; j < 4; j++) { wmx[i][j] = expf(w_mix[i * 4 + j] - mx); s += wmx[i][j]; }
            #pragma unroll
            for (int j = 0; j < 4; j++) wmx[i][j] /= s;
        }
        float s1m = 0, s2m = 0, s3m = 0, lm = 0;
        #pragma unroll
        for (int n = 0; n < 4; n++) {
            s1m += wmx[0][n] * s_s1[n][d];
            s2m += wmx[1][n] * s_s2[n][d];
            s3m += wmx[2][n] * s_s3[n][d];
            lm  += wmx[3][n] * s_lvec[n][d];
        }
        float a0 = alpha[0], a1 = alpha[1];
        s_fm[d] = s1m + a0 * (s1m - s2m) + a1 * (s1m - s3m);
        s_lm[d] = lm;
    }
    __syncthreads();

    if (warp == 0) {
        float x = s_fm[lane] * gate_w[lane] + s_fm[lane + 32] * gate_w[lane + 32]
                + s_lm[lane] * gate_w[64 + lane] + s_lm[lane + 32] * gate_w[96 + lane];
        #pragma unroll
        for (int o = 16; o > 0; o >>= 1) x += __shfl_xor_sync(0xffffffffu, x, o);
        if (lane == 0) s_g[4] = sigmoidf_(x + gate_b[0]);
    }
    __syncthreads();

    if (t < 64) {
        float gm = s_g[4];
        float fin = gm * s_fm[t] + (1.f - gm) * s_lm[t];
        g_final[(size_t)b * 64 + t] = fin;
        g_Amat[(size_t)b * 128 + t] = fin;
        g_Amat[(size_t)b * 128 + 64 + t] = s_eu[t];
    }
}

// ---------------- tiled "NT" GEMM: C[i,j] = sum_k A[i,k]*B[j,k] (+bias[j]) ----------------
// 128x128 tile, 8x8 micro-tile per thread, f32x2 packed FMA.
template<int KDIM, bool BIAS>
__global__ __launch_bounds__(256) void gemm_nt_kernel(
    const float* __restrict__ Amat, const float* __restrict__ Bmat,
    const float* __restrict__ bias, float* __restrict__ Cmat,
    int Mrows, int Ncols)
{
    __shared__ float As[16][128];
    __shared__ float Bs[16][128];
    int t = threadIdx.x;
    int tx = t & 15, ty = t >> 4;
    int row0 = blockIdx.y * 128, col0 = blockIdx.x * 128;

    u64 acc[8][4];
    #pragma unroll
    for (int r = 0; r < 8; r++)
        #pragma unroll
        for (int c = 0; c < 4; c++) acc[r][c] = 0ULL;

    int lr = t >> 1;
    int lk = (t & 1) * 8;
    int arow = min(row0 + lr, Mrows - 1);
    int brow = min(col0 + lr, Ncols - 1);
    const float* aptr = Amat + (size_t)arow * KDIM + lk;
    const float* bptr = Bmat + (size_t)brow * KDIM + lk;

    for (int k0 = 0; k0 < KDIM; k0 += 16) {
        float4 a0 = *(const float4*)(aptr + k0);
        float4 a1 = *(const float4*)(aptr + k0 + 4);
        float4 b0 = *(const float4*)(bptr + k0);
        float4 b1 = *(const float4*)(bptr + k0 + 4);
        As[lk + 0][lr] = a0.x; As[lk + 1][lr] = a0.y; As[lk + 2][lr] = a0.z; As[lk + 3][lr] = a0.w;
        As[lk + 4][lr] = a1.x; As[lk + 5][lr] = a1.y; As[lk + 6][lr] = a1.z; As[lk + 7][lr] = a1.w;
        Bs[lk + 0][lr] = b0.x; Bs[lk + 1][lr] = b0.y; Bs[lk + 2][lr] = b0.z; Bs[lk + 3][lr] = b0.w;
        Bs[lk + 4][lr] = b1.x; Bs[lk + 5][lr] = b1.y; Bs[lk + 6][lr] = b1.z; Bs[lk + 7][lr] = b1.w;
        __syncthreads();
        #pragma unroll
        for (int k = 0; k < 16; k++) {
            float a[8];
            *(float4*)&a[0] = *(const float4*)&As[k][ty * 8];
            *(float4*)&a[4] = *(const float4*)&As[k][ty * 8 + 4];
            u64 bp[4];
            const u64* bb = (const u64*)&Bs[k][tx * 8];
            bp[0] = bb[0]; bp[1] = bb[1]; bp[2] = bb[2]; bp[3] = bb[3];
            #pragma unroll
            for (int r = 0; r < 8; r++) {
                u64 ar = bcast2(a[r]);
                fma2(acc[r][0], ar, bp[0]);
                fma2(acc[r][1], ar, bp[1]);
                fma2(acc[r][2], ar, bp[2]);
                fma2(acc[r][3], ar, bp[3]);
            }
        }
        __syncthreads();
    }

    int cb = col0 + tx * 8;
    bool fullcol = (cb + 8 <= Ncols);
    #pragma unroll
    for (int r = 0; r < 8; r++) {
        int gr = row0 + ty * 8 + r;
        if (gr >= Mrows) continue;
        float v[8];
        #pragma unroll
        for (int c = 0; c < 4; c++) unpk2(acc[r][c], v[2 * c], v[2 * c + 1]);
        size_t base = (size_t)gr * Ncols + cb;
        if (fullcol) {
            if (BIAS) {
                #pragma unroll
                for (int c = 0; c < 8; c++) v[c] += bias[cb + c];
            }
            *(float4*)&Cmat[base]     = make_float4(v[0], v[1], v[2], v[3]);
            *(float4*)&Cmat[base + 4] = make_float4(v[4], v[5], v[6], v[7]);
        } else {
            for (int c = 0; c < 8; c++) {
                if (cb + c < Ncols)
                    Cmat[base + c] = v[c] + (BIAS ? bias[cb + c] : 0.f);
            }
        }
    }
}

// ---------------- old-item corrections (one warp per (b, flat j); deterministic) ----------------
__global__ __launch_bounds__(256) void correction_kernel(
    const int* __restrict__ oldIt, const float* __restrict__ item_emb,
    float* __restrict__ out)
{
    int gw = (blockIdx.x * blockDim.x + threadIdx.x) >> 5;
    int lane = threadIdx.x & 31;
    if (gw >= BB * 80) return;
    int b = gw / 80, jf = gw % 80;
    int e = oldIt[((size_t)(jf / NOLDK) * BB + b) * NOLDK + (jf % NOLDK)];
    // first-occurrence dedup over the flattened 80-entry list for this b
    for (int p = 0; p < jf; p++) {
        if (oldIt[((size_t)(p / NOLDK) * BB + b) * NOLDK + (p % NOLDK)] == e) return;
    }
    float c0 = 0.f, c1 = 0.f;
    #pragma unroll
    for (int n2 = 0; n2 < 4; n2++) {
        bool mem = false;
        #pragma unroll
        for (int j2 = 0; j2 < NOLDK; j2++)
            mem = mem || (oldIt[((size_t)n2 * BB + b) * NOLDK + j2] == e);
        if (mem) {
            c0 += g_final_each[((size_t)n2 * BB + b) * 64 + lane]      - g_final[(size_t)b * 64 + lane];
            c1 += g_final_each[((size_t)n2 * BB + b) * 64 + lane + 32] - g_final[(size_t)b * 64 + lane + 32];
        }
    }
    float dot = c0 * item_emb[(size_t)(e + 1) * 64 + lane]
              + c1 * item_emb[(size_t)(e + 1) * 64 + lane + 32];
    #pragma unroll
    for (int o = 16; o > 0; o >>= 1) dot += __shfl_xor_sync(0xffffffffu, dot, o);
    if (lane == 0) out[(size_t)b * NB_ITEMS + e] += dot;  // unique writer per (b,e)
}

// ---------------- launch ----------------
extern "C" void kernel_launch(void* const* d_in, const int* in_sizes, int n_in,
                              void* d_out, int out_size)
{
    const int*   click    = (const int*)d_in[0];
    const int*   favor    = (const int*)d_in[1];
    const int*   cart     = (const int*)d_in[2];
    const int*   buy      = (const int*)d_in[3];
    const int*   userData = (const int*)d_in[4];
    const int*   oldIt    = (const int*)d_in[5];
    const float* item_emb = (const float*)d_in[6];
    const float* user_emb = (const float*)d_in[7];
    const float* user_wd  = (const float*)d_in[8];
    const float* omiga    = (const float*)d_in[9];
    const float* w_mix    = (const float*)d_in[10];
    const float* alpha    = (const float*)d_in[11];
    const float* gate_w   = (const float*)d_in[12];
    const float* gate_b   = (const float*)d_in[13];
    const float* Wk       = (const float*)d_in[14];
    const float* bk       = (const float*)d_in[15];
    const float* u_w      = (const float*)d_in[16];
    const float* u_b      = (const float*)d_in[17];
    float* out = (float*)d_out;

    void *pA = nullptr, *pB = nullptr;
    cudaGetSymbolAddress(&pA, g_Amat);
    cudaGetSymbolAddress(&pB, g_Bbig);

    // 1. Bbig + omiga copy
    prep_kernel<<<(NB_ITEMS * 128 + 255) / 256, 256>>>(item_emb, u_w, omiga, out);

    // 2. per-batch front-end
    batch_kernel<<<BB, 256>>>(click, favor, cart, buy, userData, item_emb, user_emb,
                              user_wd, w_mix, alpha, gate_w, gate_b, Wk, bk);

    // 3. score base: [final|e_user] @ [e_all^T; u_w]  + u_b
    {
        dim3 grid((NB_ITEMS + 127) / 128, (BB + 127) / 128);
        gemm_nt_kernel<128, true><<<grid, 256>>>((const float*)pA, (const float*)pB,
                                                 u_b, out, BB, NB_ITEMS);
    }

    // 4. old-item corrections (after base score written)
    correction_kernel<<<(BB * 80 * 32 + 255) / 256, 256>>>(oldIt, item_emb, out);

    // 5. sim = e_all @ e_all^T
    {
        dim3 grid((NB_ITEMS + 127) / 128, (NB_ITEMS + 127) / 128);
        gemm_nt_kernel<64, false><<<grid, 256>>>(item_emb + 64, item_emb + 64,
                                                 nullptr, out + SIM_OFF,
                                                 NB_ITEMS, NB_ITEMS);
    }
}

// round 2
// speedup vs baseline: 1.4505x; 1.4505x over previous
#include <cuda_runtime.h>

#define NB_ITEMS 12000
#define DD 64
#define BB 1024
#define LL 20
#define BKK 10
#define NOLDK 20

#define SIM_OFF   ((size_t)BB * NB_ITEMS)                     /* 12,288,000 */
#define OMIGA_OFF (SIM_OFF + (size_t)NB_ITEMS * NB_ITEMS)     /* 156,288,000 */

// ---------------- scratch (static device globals; no allocation) ----------------
__device__ float g_final_each[4 * BB * DD];   // [n][b][d]
__device__ float g_final[BB * DD];            // [b][d]
__device__ float g_Amat[BB * 128];            // [b][0:64)=final, [64:128)=e_user
__device__ float g_Bbig[(size_t)NB_ITEMS * 128]; // [e][0:64)=item_emb[1+e], [64:128)=u_w[:,e]

// ---------------- f32x2 helpers (packed fp32 FMA, sm_100+) ----------------
typedef unsigned long long u64;
__device__ __forceinline__ u64 bcast2(float x) {
    u64 r; asm("mov.b64 %0, {%1, %1};" : "=l"(r) : "f"(x)); return r;
}
__device__ __forceinline__ void fma2(u64& d, u64 a, u64 b) {
    asm("fma.rn.f32x2 %0, %1, %2, %0;" : "+l"(d) : "l"(a), "l"(b));
}
__device__ __forceinline__ void unpk2(u64 v, float& lo, float& hi) {
    asm("mov.b64 {%0, %1}, %2;" : "=f"(lo), "=f"(hi) : "l"(v));
}
__device__ __forceinline__ float sigmoidf_(float x) { return 1.f / (1.f + expf(-x)); }

// ---------------- prep: build Bbig (e_all || u_w^T) and copy omiga ----------------
__global__ __launch_bounds__(256) void prep_kernel(
    const float* __restrict__ item_emb, const float* __restrict__ u_w,
    const float* __restrict__ omiga, float* __restrict__ out)
{
    int idx = blockIdx.x * blockDim.x + threadIdx.x;
    if (idx < NB_ITEMS * 128) {
        int e = idx >> 7, k = idx & 127;
        g_Bbig[idx] = (k < 64) ? item_emb[(size_t)(e + 1) * 64 + k]
                               : u_w[(size_t)(k - 64) * NB_ITEMS + e];
    }
    if (idx < NB_ITEMS) out[OMIGA_OFF + idx] = omiga[idx + 1];
}

// ---------------- per-batch kernel: baskets/attn/ema/gates/mix ----------------
__global__ __launch_bounds__(256) void batch_kernel(
    const int* __restrict__ click, const int* __restrict__ favor,
    const int* __restrict__ cart, const int* __restrict__ buy,
    const int* __restrict__ userData,
    const float* __restrict__ item_emb, const float* __restrict__ user_emb,
    const float* __restrict__ user_wd, const float* __restrict__ w_mix,
    const float* __restrict__ alpha, const float* __restrict__ gate_w,
    const float* __restrict__ gate_b, const float* __restrict__ Wk,
    const float* __restrict__ bk)
{
    __shared__ float s_bask[4][LL][DD];
    __shared__ int   s_idx[4][LL][BKK];
    __shared__ float s_eu[DD];
    __shared__ float s_scp[4][2][LL];
    __shared__ float s_attn[4][LL];
    __shared__ float s_mask[4][LL];
    __shared__ float s_lvec[4][DD];
    __shared__ float s_s1[4][DD], s_s2[4][DD], s_s3[4][DD], s_fn[4][DD];
    __shared__ float s_g[8];
    __shared__ float s_fm[DD], s_lm[DD];

    int b = blockIdx.x, t = threadIdx.x;
    int lane = t & 31, warp = t >> 5;
    int u = userData[b];
    const int* srcs[4] = {click, favor, cart, buy};

    for (int i = t; i < 4 * LL * BKK; i += 256) {
        int n = i / (LL * BKK), r = i % (LL * BKK);
        s_idx[n][r / BKK][r % BKK] = srcs[n][(size_t)b * LL * BKK + r];
    }
    if (t < 64) s_eu[t] = user_emb[(size_t)u * 64 + t];
    __syncthreads();

    // baskets: sum of 10 gathered embeddings per (n,l,d)
    for (int i = t; i < 4 * LL * DD; i += 256) {
        int n = i / (LL * DD), rem = i % (LL * DD), l = rem / DD, d = rem & 63;
        float s = 0.f;
        #pragma unroll
        for (int q = 0; q < BKK; q++) s += item_emb[(size_t)s_idx[n][l][q] * 64 + d];
        s_bask[n][l][d] = s;
    }
    __syncthreads();

    // posmask
    if (t < 80) {
        int n = t / LL, l = t % LL;
        float m = 0.f;
        for (int d = 0; d < DD; d++) m += s_bask[n][l][d];
        s_mask[n][l] = (m != 0.f) ? 1.f : 0.f;
    }

    // k = relu(bask @ Wk[n] + bk), scores = e_user . k   (thread = (n,e))
    {
        int n = t >> 6, e = t & 63;
        float acc[LL];
        #pragma unroll
        for (int l = 0; l < LL; l++) acc[l] = bk[n * 64 + e];
        for (int d0 = 0; d0 < DD; d0++) {
            float w = Wk[((size_t)n * 64 + d0) * 64 + e];
            #pragma unroll
            for (int l = 0; l < LL; l++) acc[l] += s_bask[n][l][d0] * w;
        }
        float eu = s_eu[e];
        #pragma unroll
        for (int l = 0; l < LL; l++) {
            float v = fmaxf(acc[l], 0.f) * eu;
            #pragma unroll
            for (int o = 16; o > 0; o >>= 1) v += __shfl_xor_sync(0xffffffffu, v, o);
            if (lane == 0) s_scp[n][e >> 5][l] = v;
        }
    }
    __syncthreads();

    // softmax over l per n
    if (warp < 4) {
        int n = warp;
        float sc = -1e30f;
        if (lane < LL) {
            sc = (s_scp[n][0][lane] + s_scp[n][1][lane]) * 0.125f;
            if (s_mask[n][lane] == 0.f) sc = -1e9f;
        }
        float mx = sc;
        #pragma unroll
        for (int o = 16; o > 0; o >>= 1) mx = fmaxf(mx, __shfl_xor_sync(0xffffffffu, mx, o));
        float ex = (lane < LL) ? expf(sc - mx) : 0.f;
        float sm = ex;
        #pragma unroll
        for (int o = 16; o > 0; o >>= 1) sm += __shfl_xor_sync(0xffffffffu, sm, o);
        if (lane < LL) s_attn[n][lane] = ex / sm;
    }
    __syncthreads();

    // l_vec + EMA (thread = (n,d))
    {
        int n = t >> 6, d = t & 63;
        float lv = 0.f;
        #pragma unroll
        for (int l = 0; l < LL; l++) lv += s_attn[n][l] * s_bask[n][l][d];
        s_lvec[n][d] = lv;
        float w1 = sigmoidf_(user_wd[(size_t)u * 8 + 2 * n]);
        float w2 = sigmoidf_(user_wd[(size_t)u * 8 + 2 * n + 1]);
        float coef = 1.f - w2 * w1;
        float h = s_bask[n][0][d];
        #pragma unroll
        for (int l = 1; l < LL; l++) h = w1 * h + coef * s_bask[n][l][d];
        float s1 = h;
        h = s_bask[n][10][d];
        #pragma unroll
        for (int l = 11; l < LL; l++) h = w1 * h + coef * s_bask[n][l][d];
        float s2 = h;
        float s3 = w1 * s_bask[n][18][d] + coef * s_bask[n][19][d];
        float a0 = alpha[0], a1 = alpha[1];
        float fn = s1 + a0 * (s1 - s2) + a1 * (s1 - s3);
        s_s1[n][d] = s1; s_s2[n][d] = s2; s_s3[n][d] = s3; s_fn[n][d] = fn;
    }
    __syncthreads();

    // per-n gate
    if (warp < 4) {
        int n = warp;
        float x = s_fn[n][lane] * gate_w[lane] + s_fn[n][lane + 32] * gate_w[lane + 32]
                + s_lvec[n][lane] * gate_w[64 + lane] + s_lvec[n][lane + 32] * gate_w[96 + lane];
        #pragma unroll
        for (int o = 16; o > 0; o >>= 1) x += __shfl_xor_sync(0xffffffffu, x, o);
        if (lane == 0) s_g[n] = sigmoidf_(x + gate_b[0]);
    }
    __syncthreads();

    {
        int n = t >> 6, d = t & 63;
        float g = s_g[n];
        g_final_each[((size_t)n * BB + b) * 64 + d] = g * s_fn[n][d] + (1.f - g) * s_lvec[n][d];
    }

    // w_mix softmax + mixed streams
    if (t < 64) {
        int d = t;
        float wmx[4][4];
        #pragma unroll
        for (int i = 0; i < 4; i++) {
            float mx = -1e30f;
            #pragma unroll
            for (int j = 0; j < 4; j++) mx = fmaxf(mx, w_mix[i * 4 + j]);
            float s = 0.f;
            #pragma unroll
            for (int j = 0; j < 4; j++) { wmx[i][j] = expf(w_mix[i * 4 + j] - mx); s += wmx[i][j]; }
            #pragma unroll
            for (int j = 0; j < 4; j++) wmx[i][j] /= s;
        }
        float s1m = 0, s2m = 0, s3m = 0, lm = 0;
        #pragma unroll
        for (int n = 0; n < 4; n++) {
            s1m += wmx[0][n] * s_s1[n][d];
            s2m += wmx[1][n] * s_s2[n][d];
            s3m += wmx[2][n] * s_s3[n][d];
            lm  += wmx[3][n] * s_lvec[n][d];
        }
        float a0 = alpha[0], a1 = alpha[1];
        s_fm[d] = s1m + a0 * (s1m - s2m) + a1 * (s1m - s3m);
        s_lm[d] = lm;
    }
    __syncthreads();

    if (warp == 0) {
        float x = s_fm[lane] * gate_w[lane] + s_fm[lane + 32] * gate_w[lane + 32]
                + s_lm[lane] * gate_w[64 + lane] + s_lm[lane + 32] * gate_w[96 + lane];
        #pragma unroll
        for (int o = 16; o > 0; o >>= 1) x += __shfl_xor_sync(0xffffffffu, x, o);
        if (lane == 0) s_g[4] = sigmoidf_(x + gate_b[0]);
    }
    __syncthreads();

    if (t < 64) {
        float gm = s_g[4];
        float fin = gm * s_fm[t] + (1.f - gm) * s_lm[t];
        g_final[(size_t)b * 64 + t] = fin;
        g_Amat[(size_t)b * 128 + t] = fin;
        g_Amat[(size_t)b * 128 + 64 + t] = s_eu[t];
    }
}

// ---------------- tiled "NT" GEMM: C[i,j] = sum_k A[i,k]*B[j,k] (+bias[j]) ----------------
// 128x128 tile, 8x8 micro-tile per thread mapped (ty*4, ty*4+64) x (tx*4, tx*4+64)
// so all fragment loads are conflict-free LDS.128. f32x2 packed FMA.
// SYMM: compute only block-upper-triangle; mirror-write transpose tile via smem.
template<int KDIM, bool BIAS, bool SYMM>
__global__ __launch_bounds__(256) void gemm_nt_kernel(
    const float* __restrict__ Amat, const float* __restrict__ Bmat,
    const float* __restrict__ bias, float* __restrict__ Cmat,
    int Mrows, int Ncols)
{
    __shared__ float sm[2 * 16 * 128];   // As | Bs ; reused as transpose buffer
    float* As = sm;
    float* Bs = sm + 16 * 128;

    int bx = blockIdx.x, by = blockIdx.y;
    if (SYMM && bx < by) return;
    int t = threadIdx.x;
    int tx = t & 15, ty = t >> 4;
    int row0 = by * 128, col0 = bx * 128;

    u64 acc[8][4];
    #pragma unroll
    for (int r = 0; r < 8; r++)
        #pragma unroll
        for (int c = 0; c < 4; c++) acc[r][c] = 0ULL;

    int lr = t >> 1;
    int lk = (t & 1) * 8;
    int arow = min(row0 + lr, Mrows - 1);
    int brow = min(col0 + lr, Ncols - 1);
    const float* aptr = Amat + (size_t)arow * KDIM + lk;
    const float* bptr = Bmat + (size_t)brow * KDIM + lk;

    for (int k0 = 0; k0 < KDIM; k0 += 16) {
        float4 a0 = *(const float4*)(aptr + k0);
        float4 a1 = *(const float4*)(aptr + k0 + 4);
        float4 b0 = *(const float4*)(bptr + k0);
        float4 b1 = *(const float4*)(bptr + k0 + 4);
        As[(lk + 0) * 128 + lr] = a0.x; As[(lk + 1) * 128 + lr] = a0.y;
        As[(lk + 2) * 128 + lr] = a0.z; As[(lk + 3) * 128 + lr] = a0.w;
        As[(lk + 4) * 128 + lr] = a1.x; As[(lk + 5) * 128 + lr] = a1.y;
        As[(lk + 6) * 128 + lr] = a1.z; As[(lk + 7) * 128 + lr] = a1.w;
        Bs[(lk + 0) * 128 + lr] = b0.x; Bs[(lk + 1) * 128 + lr] = b0.y;
        Bs[(lk + 2) * 128 + lr] = b0.z; Bs[(lk + 3) * 128 + lr] = b0.w;
        Bs[(lk + 4) * 128 + lr] = b1.x; Bs[(lk + 5) * 128 + lr] = b1.y;
        Bs[(lk + 6) * 128 + lr] = b1.z; Bs[(lk + 7) * 128 + lr] = b1.w;
        __syncthreads();
        #pragma unroll
        for (int k = 0; k < 16; k++) {
            float4 fa0 = *(const float4*)&As[k * 128 + ty * 4];
            float4 fa1 = *(const float4*)&As[k * 128 + 64 + ty * 4];
            const u64* pb0 = (const u64*)&Bs[k * 128 + tx * 4];
            const u64* pb1 = (const u64*)&Bs[k * 128 + 64 + tx * 4];
            u64 bq0 = pb0[0], bq1 = pb0[1], bq2 = pb1[0], bq3 = pb1[1];
            float a[8] = {fa0.x, fa0.y, fa0.z, fa0.w, fa1.x, fa1.y, fa1.z, fa1.w};
            #pragma unroll
            for (int r = 0; r < 8; r++) {
                u64 ar = bcast2(a[r]);
                fma2(acc[r][0], ar, bq0);
                fma2(acc[r][1], ar, bq1);
                fma2(acc[r][2], ar, bq2);
                fma2(acc[r][3], ar, bq3);
            }
        }
        __syncthreads();
    }

    // unpack accumulators: vv[r][c] with r,c in 0..7 (local micro-tile coords)
    float vv[8][8];
    #pragma unroll
    for (int r = 0; r < 8; r++)
        #pragma unroll
        for (int c = 0; c < 4; c++) unpk2(acc[r][c], vv[r][2 * c], vv[r][2 * c + 1]);

    int cb0 = col0 + tx * 4;
    int cb1 = cb0 + 64;
    // normal write
    #pragma unroll
    for (int r = 0; r < 8; r++) {
        int gr = row0 + (r < 4 ? ty * 4 + r : 64 + ty * 4 + (r - 4));
        if (gr >= Mrows) continue;
        size_t base = (size_t)gr * Ncols;
        if (cb0 + 4 <= Ncols) {
            float4 o;
            o.x = vv[r][0]; o.y = vv[r][1]; o.z = vv[r][2]; o.w = vv[r][3];
            if (BIAS) { o.x += bias[cb0]; o.y += bias[cb0+1]; o.z += bias[cb0+2]; o.w += bias[cb0+3]; }
            *(float4*)&Cmat[base + cb0] = o;
        } else {
            for (int c = 0; c < 4; c++)
                if (cb0 + c < Ncols) Cmat[base + cb0 + c] = vv[r][c] + (BIAS ? bias[cb0 + c] : 0.f);
        }
        if (cb1 + 4 <= Ncols) {
            float4 o;
            o.x = vv[r][4]; o.y = vv[r][5]; o.z = vv[r][6]; o.w = vv[r][7];
            if (BIAS) { o.x += bias[cb1]; o.y += bias[cb1+1]; o.z += bias[cb1+2]; o.w += bias[cb1+3]; }
            *(float4*)&Cmat[base + cb1] = o;
        } else {
            for (int c = 0; c < 4; c++)
                if (cb1 + c < Ncols) Cmat[base + cb1 + c] = vv[r][c + 4] + (BIAS ? bias[cb1 + c] : 0.f);
        }
    }

    // mirror write (symmetric case, off-diagonal blocks): C[col, row] = value
    if (SYMM && bx > by) {
        float (*buf)[132] = (float (*)[132])sm;   // 16 x 132 floats, fits in 4096
        #pragma unroll 1
        for (int cr = 0; cr < 8; cr++) {
            __syncthreads();
            int qc = cr >> 2;              // which 64-column half
            int txsel = (cr & 3) * 4;      // participating tx range
            if (tx >= txsel && tx < txsel + 4) {
                #pragma unroll
                for (int cc = 0; cc < 4; cc++) {
                    int cl = (tx - txsel) * 4 + cc;        // 0..15 local col in round
                    int lc = qc * 4 + cc;                   // index into vv cols
                    float4 lo, hi;
                    lo.x = vv[0][lc]; lo.y = vv[1][lc]; lo.z = vv[2][lc]; lo.w = vv[3][lc];
                    hi.x = vv[4][lc]; hi.y = vv[5][lc]; hi.z = vv[6][lc]; hi.w = vv[7][lc];
                    *(float4*)&buf[cl][ty * 4]      = lo;
                    *(float4*)&buf[cl][64 + ty * 4] = hi;
                }
            }
            __syncthreads();
            #pragma unroll
            for (int it = 0; it < 2; it++) {
                int idx = t + it * 256;            // 0..511
                int br2 = idx >> 5, ch = idx & 31;
                int orow = col0 + cr * 16 + br2;   // output row = original col
                int oc = row0 + ch * 4;            // output col = original row
                if (orow < Ncols) {
                    if (oc + 4 <= Mrows) {
                        *(float4*)&Cmat[(size_t)orow * Ncols + oc] = *(float4*)&buf[br2][ch * 4];
                    } else {
                        for (int c = 0; c < 4; c++)
                            if (oc + c < Mrows)
                                Cmat[(size_t)orow * Ncols + oc + c] = buf[br2][ch * 4 + c];
                    }
                }
            }
        }
    }
}

// ---------------- old-item corrections: one block per b, all state in smem ----------------
__global__ __launch_bounds__(256) void correction_kernel(
    const int* __restrict__ oldIt, const float* __restrict__ item_emb,
    float* __restrict__ out)
{
    __shared__ int   s_e[80];
    __shared__ int   s_first[80];
    __shared__ float s_delta[4][64];

    int b = blockIdx.x, t = threadIdx.x;
    int warp = t >> 5, lane = t & 31;

    if (t < 80) {
        int n = t / NOLDK, j = t % NOLDK;
        s_e[t] = oldIt[((size_t)n * BB + b) * NOLDK + j];
    }
    {
        int n = t >> 6, d = t & 63;
        s_delta[n][d] = g_final_each[((size_t)n * BB + b) * 64 + d]
                      - g_final[(size_t)b * 64 + d];
    }
    __syncthreads();
    if (t < 80) {
        int e = s_e[t], first = 1;
        for (int p = 0; p < t; p++) if (s_e[p] == e) { first = 0; break; }
        s_first[t] = first;
    }
    __syncthreads();

    for (int j = warp; j < 80; j += 8) {
        if (!s_first[j]) continue;
        int e = s_e[j];
        float c0 = 0.f, c1 = 0.f;
        #pragma unroll
        for (int n = 0; n < 4; n++) {
            bool mem = false;
            #pragma unroll
            for (int q = 0; q < NOLDK; q++) mem = mem || (s_e[n * NOLDK + q] == e);
            if (mem) { c0 += s_delta[n][lane]; c1 += s_delta[n][lane + 32]; }
        }
        float dot = c0 * item_emb[(size_t)(e + 1) * 64 + lane]
                  + c1 * item_emb[(size_t)(e + 1) * 64 + lane + 32];
        #pragma unroll
        for (int o = 16; o > 0; o >>= 1) dot += __shfl_xor_sync(0xffffffffu, dot, o);
        if (lane == 0) out[(size_t)b * NB_ITEMS + e] += dot;  // unique writer per (b,e)
    }
}

// ---------------- launch ----------------
extern "C" void kernel_launch(void* const* d_in, const int* in_sizes, int n_in,
                              void* d_out, int out_size)
{
    const int*   click    = (const int*)d_in[0];
    const int*   favor    = (const int*)d_in[1];
    const int*   cart     = (const int*)d_in[2];
    const int*   buy      = (const int*)d_in[3];
    const int*   userData = (const int*)d_in[4];
    const int*   oldIt    = (const int*)d_in[5];
    const float* item_emb = (const float*)d_in[6];
    const float* user_emb = (const float*)d_in[7];
    const float* user_wd  = (const float*)d_in[8];
    const float* omiga    = (const float*)d_in[9];
    const float* w_mix    = (const float*)d_in[10];
    const float* alpha    = (const float*)d_in[11];
    const float* gate_w   = (const float*)d_in[12];
    const float* gate_b   = (const float*)d_in[13];
    const float* Wk       = (const float*)d_in[14];
    const float* bk       = (const float*)d_in[15];
    const float* u_w      = (const float*)d_in[16];
    const float* u_b      = (const float*)d_in[17];
    float* out = (float*)d_out;

    void *pA = nullptr, *pB = nullptr;
    cudaGetSymbolAddress(&pA, g_Amat);
    cudaGetSymbolAddress(&pB, g_Bbig);

    // 1. Bbig + omiga copy
    prep_kernel<<<(NB_ITEMS * 128 + 255) / 256, 256>>>(item_emb, u_w, omiga, out);

    // 2. per-batch front-end
    batch_kernel<<<BB, 256>>>(click, favor, cart, buy, userData, item_emb, user_emb,
                              user_wd, w_mix, alpha, gate_w, gate_b, Wk, bk);

    // 3. score base: [final|e_user] @ [e_all^T; u_w]  + u_b
    {
        dim3 grid((NB_ITEMS + 127) / 128, (BB + 127) / 128);
        gemm_nt_kernel<128, true, false><<<grid, 256>>>((const float*)pA, (const float*)pB,
                                                        u_b, out, BB, NB_ITEMS);
    }

    // 4. old-item corrections (after base score written)
    correction_kernel<<<BB, 256>>>(oldIt, item_emb, out);

    // 5. sim = e_all @ e_all^T  (symmetric: upper block triangle + mirrored writes)
    {
        dim3 grid((NB_ITEMS + 127) / 128, (NB_ITEMS + 127) / 128);
        gemm_nt_kernel<64, false, true><<<grid, 256>>>(item_emb + 64, item_emb + 64,
                                                       nullptr, out + SIM_OFF,
                                                       NB_ITEMS, NB_ITEMS);
    }
}